// round 1
// baseline (speedup 1.0000x reference)
#include <cuda_runtime.h>

// Stickbreaking attention, fp32, B=2 H=16 S=1024 D=64.
//
// w[i,k] = sigmoid(x_ik) * exp( sum_{j=k..i} logsigmoid(-x_ij) )
//        = exp( x_ik + lb_ik + S_ik ),  lb = logsigmoid(-x) <= 0,
//          S_ik = suffix sum of lb over keys k..i  (<= 0, stable).
// Stream key blocks in DESCENDING order, carrying per-row accumulator A_i.

#define SEQ     1024
#define DHEAD   64
#define BQ      32          // query rows per tile
#define BK      64          // keys per block
#define THREADS 128
#define NQB     (SEQ / BQ)  // 32 q-tiles

// XOR swizzle on float4 chunks: row r (0..63), chunk c4 (0..15)
__device__ __forceinline__ int swz(int r, int c4) {
    return r * 16 + (c4 ^ ((r >> 2) & 15));
}

__global__ __launch_bounds__(THREADS, 4)
void stickbreaking_kernel(const float* __restrict__ q,
                          const float* __restrict__ k,
                          const float* __restrict__ v,
                          float* __restrict__ out) {
    __shared__ float4 Qs[BQ * 16];   // 8 KB  (swizzled)
    __shared__ float4 Ks[BK * 16];   // 16 KB
    __shared__ float4 Vs[BK * 16];   // 16 KB
    __shared__ float4 Ws[BQ * 16];   // 8 KB

    const int tid = threadIdx.x;
    const int rg  = tid >> 4;   // 0..7  : rows 4*rg .. 4*rg+3 (of BQ)
    const int kg  = tid & 15;   // 0..15 : keys 4*kg .. 4*kg+3 (of BK)
    const int bh  = blockIdx.y;
    const int x   = blockIdx.x; // pair id 0..15

    const float* qb_base = q   + (size_t)bh * SEQ * DHEAD;
    const float* kb_base = k   + (size_t)bh * SEQ * DHEAD;
    const float* vb_base = v   + (size_t)bh * SEQ * DHEAD;
    float*       ob_base = out + (size_t)bh * SEQ * DHEAD;

    #pragma unroll 1
    for (int tsel = 0; tsel < 2; ++tsel) {
        const int qb    = tsel ? (NQB - 1 - x) : x;   // pair x with 31-x -> uniform work
        const int qbase = qb * BQ;

        __syncthreads();  // protect Qs reuse across tiles

        // ---- load Q tile [BQ x 64], swizzled ----
        {
            const float4* g = (const float4*)(qb_base + (size_t)qbase * DHEAD);
            #pragma unroll
            for (int i = 0; i < 4; i++) {
                int f = i * THREADS + tid;          // float4 index 0..511
                int r = f >> 4, c4 = f & 15;
                Qs[swz(r, c4)] = g[f];
            }
        }

        float acc[4][4];
        #pragma unroll
        for (int i = 0; i < 4; i++)
            #pragma unroll
            for (int j = 0; j < 4; j++) acc[i][j] = 0.f;
        float A[4] = {0.f, 0.f, 0.f, 0.f};

        const int nkb = qb / 2 + 1;  // key blocks covering keys 0 .. qbase+31

        #pragma unroll 1
        for (int kb = nkb - 1; kb >= 0; --kb) {
            const int kbase = kb * BK;

            __syncthreads();  // prev PV done before overwriting K/V
            {
                const float4* gk = (const float4*)(kb_base + (size_t)kbase * DHEAD);
                const float4* gv = (const float4*)(vb_base + (size_t)kbase * DHEAD);
                #pragma unroll
                for (int i = 0; i < 8; i++) {
                    int f = i * THREADS + tid;      // float4 index 0..1023
                    int r = f >> 4, c4 = f & 15;
                    Ks[swz(r, c4)] = gk[f];
                    Vs[swz(r, c4)] = gv[f];
                }
            }
            __syncthreads();

            // ---- QK^T : 4x4 score tile per thread ----
            float s[4][4];
            #pragma unroll
            for (int i = 0; i < 4; i++)
                #pragma unroll
                for (int j = 0; j < 4; j++) s[i][j] = 0.f;

            #pragma unroll
            for (int d4 = 0; d4 < 16; ++d4) {
                float4 qv[4], kv[4];
                #pragma unroll
                for (int i = 0; i < 4; i++) qv[i] = Qs[(4 * rg + i) * 16 + (d4 ^ rg)];
                #pragma unroll
                for (int j = 0; j < 4; j++) kv[j] = Ks[(4 * kg + j) * 16 + (d4 ^ kg)];
                #pragma unroll
                for (int i = 0; i < 4; i++)
                    #pragma unroll
                    for (int j = 0; j < 4; j++) {
                        s[i][j] = fmaf(qv[i].x, kv[j].x, s[i][j]);
                        s[i][j] = fmaf(qv[i].y, kv[j].y, s[i][j]);
                        s[i][j] = fmaf(qv[i].z, kv[j].z, s[i][j]);
                        s[i][j] = fmaf(qv[i].w, kv[j].w, s[i][j]);
                    }
            }

            // ---- elementwise + per-row suffix scan (16 lanes per row group) ----
            float wv[4][4];
            const unsigned li = (unsigned)kg;  // lane index within 16-lane segment
            #pragma unroll
            for (int i = 0; i < 4; i++) {
                const int row_g = qbase + 4 * rg + i;
                float lb[4], c[4];
                #pragma unroll
                for (int j = 0; j < 4; j++) {
                    float xx = s[i][j] * 0.125f;  // 1/sqrt(64)
                    float l  = -(fmaxf(xx, 0.f) + __logf(1.f + __expf(-fabsf(xx))));
                    bool valid = (kbase + 4 * kg + j) <= row_g;
                    lb[j] = valid ? l : 0.f;
                    c[j]  = valid ? (xx + l) : -1e30f;   // exp -> 0 for masked
                }
                float tloc = lb[0] + lb[1] + lb[2] + lb[3];
                float incl = tloc;  // inclusive suffix sum over 16 lanes (keys ascending)
                #pragma unroll
                for (int dlt = 1; dlt < 16; dlt <<= 1) {
                    float o = __shfl_down_sync(0xffffffffu, incl, dlt, 16);
                    if (li + dlt < 16) incl += o;
                }
                float total = __shfl_sync(0xffffffffu, incl, 0, 16);  // block row sum
                float run = A[i] + (incl - tloc);  // lb over keys with higher kg
                run += lb[3]; wv[i][3] = __expf(c[3] + run);
                run += lb[2]; wv[i][2] = __expf(c[2] + run);
                run += lb[1]; wv[i][1] = __expf(c[1] + run);
                run += lb[0]; wv[i][0] = __expf(c[0] + run);
                A[i] += total;
            }

            // ---- stage W (same-warp producers/consumers per row group) ----
            #pragma unroll
            for (int i = 0; i < 4; i++)
                Ws[(4 * rg + i) * 16 + (kg ^ rg)] =
                    make_float4(wv[i][0], wv[i][1], wv[i][2], wv[i][3]);
            __syncwarp();

            // ---- PV : out[4 rows][4 dims] += W[4 rows][:] * V[:][4 dims] ----
            #pragma unroll
            for (int j4 = 0; j4 < 16; ++j4) {
                float4 w4[4];
                #pragma unroll
                for (int i = 0; i < 4; i++) w4[i] = Ws[(4 * rg + i) * 16 + (j4 ^ rg)];
                #pragma unroll
                for (int m = 0; m < 4; m++) {
                    float4 vm = Vs[(4 * j4 + m) * 16 + (kg ^ j4)];
                    #pragma unroll
                    for (int i = 0; i < 4; i++) {
                        float wm = (m == 0) ? w4[i].x : (m == 1) ? w4[i].y
                                 : (m == 2) ? w4[i].z : w4[i].w;
                        acc[i][0] = fmaf(wm, vm.x, acc[i][0]);
                        acc[i][1] = fmaf(wm, vm.y, acc[i][1]);
                        acc[i][2] = fmaf(wm, vm.z, acc[i][2]);
                        acc[i][3] = fmaf(wm, vm.w, acc[i][3]);
                    }
                }
            }
        }

        // ---- write output tile (coalesced float4) ----
        #pragma unroll
        for (int i = 0; i < 4; i++) {
            float4 o = make_float4(acc[i][0], acc[i][1], acc[i][2], acc[i][3]);
            ((float4*)(ob_base + (size_t)(qbase + 4 * rg + i) * DHEAD))[kg] = o;
        }
    }
}

extern "C" void kernel_launch(void* const* d_in, const int* in_sizes, int n_in,
                              void* d_out, int out_size) {
    const float* q = (const float*)d_in[0];
    const float* k = (const float*)d_in[1];
    const float* v = (const float*)d_in[2];
    float* out = (float*)d_out;
    (void)in_sizes; (void)n_in; (void)out_size;

    dim3 grid(NQB / 2, 32);   // 16 balanced q-tile pairs x (B*H = 32)
    dim3 block(THREADS);
    stickbreaking_kernel<<<grid, block>>>(q, k, v, out);
}